// round 1
// baseline (speedup 1.0000x reference)
#include <cuda_runtime.h>
#include <cuda_bf16.h>

#define N_NODES  100000
#define N_EDGES  1000000
#define N_GRAPHS 1024

// ---------------- scratch (device globals; no allocation allowed) ------------
__device__ __align__(16) float g_h0  [N_NODES * 32];
__device__ __align__(16) float g_agg0[N_NODES * 32];
__device__ __align__(16) float g_h1  [N_NODES * 64];
__device__ __align__(16) float g_agg1[N_NODES * 64];
__device__ __align__(16) float g_h2  [N_NODES * 64];
__device__ __align__(16) float g_pooled[N_GRAPHS * 64];
__device__ __align__(16) int   g_counts[N_GRAPHS];

// ---------------- zero scratch each replay ----------------------------------
__global__ void zero_kernel() {
    int i = blockIdx.x * blockDim.x + threadIdx.x;
    int stride = gridDim.x * blockDim.x;
    float4 z = make_float4(0.f, 0.f, 0.f, 0.f);
    float4* a0 = (float4*)g_agg0;                 // 3.2M floats = 800k f4
    for (int j = i; j < (N_NODES * 32) / 4; j += stride) a0[j] = z;
    float4* a1 = (float4*)g_agg1;                 // 6.4M floats = 1.6M f4
    for (int j = i; j < (N_NODES * 64) / 4; j += stride) a1[j] = z;
    float4* pl = (float4*)g_pooled;
    for (int j = i; j < (N_GRAPHS * 64) / 4; j += stride) pl[j] = z;
    int4 zi = make_int4(0, 0, 0, 0);
    int4* ct = (int4*)g_counts;
    for (int j = i; j < N_GRAPHS / 4; j += stride) ct[j] = zi;
}

// ---------------- node embedding: h0 = relu([s|c] @ W_node + b) -------------
__global__ void __launch_bounds__(128) node_embed_kernel(
    const int* __restrict__ x,
    const float* __restrict__ shape_emb,
    const float* __restrict__ color_emb,
    const float* __restrict__ W_node,
    const float* __restrict__ b_node)
{
    __shared__ float sW[16 * 32];
    __shared__ float sb[32];
    __shared__ float sS[64];
    __shared__ float sC[64];
    int tid = threadIdx.x;
    for (int i = tid; i < 16 * 32; i += blockDim.x) sW[i] = W_node[i];
    if (tid < 32) sb[tid] = b_node[tid];
    if (tid < 64) sS[tid] = shape_emb[tid];
    if (tid < 64) sC[tid] = color_emb[tid];
    __syncthreads();

    int n = blockIdx.x * blockDim.x + tid;
    if (n >= N_NODES) return;
    int sh = x[2 * n];
    int co = x[2 * n + 1];

    float acc[32];
#pragma unroll
    for (int j = 0; j < 32; j++) acc[j] = sb[j];
#pragma unroll
    for (int k = 0; k < 8; k++) {
        float s = sS[sh * 8 + k];
        float c = sC[co * 8 + k];
#pragma unroll
        for (int j = 0; j < 32; j++)
            acc[j] += s * sW[k * 32 + j] + c * sW[(8 + k) * 32 + j];
    }
    float4* out = (float4*)&g_h0[(size_t)n * 32];
#pragma unroll
    for (int q = 0; q < 8; q++) {
        float4 v;
        v.x = fmaxf(acc[q * 4 + 0], 0.f);
        v.y = fmaxf(acc[q * 4 + 1], 0.f);
        v.z = fmaxf(acc[q * 4 + 2], 0.f);
        v.w = fmaxf(acc[q * 4 + 3], 0.f);
        out[q] = v;
    }
}

// ---------------- edge scatter: agg[dst] += h[src] (vector red) -------------
__device__ __forceinline__ void red_add_v4(float* p, float4 v) {
    asm volatile("red.global.add.v4.f32 [%0], {%1,%2,%3,%4};"
                 :: "l"(p), "f"(v.x), "f"(v.y), "f"(v.z), "f"(v.w)
                 : "memory");
}

template <int W4, bool L1>   // W4 = float4 chunks per row (8 for 32-wide, 16 for 64-wide)
__global__ void scatter_kernel(const int* __restrict__ src, const int* __restrict__ dst) {
    const float* hin = L1 ? g_h0 : g_h1;
    float*       agg = L1 ? g_agg0 : g_agg1;
    unsigned t = blockIdx.x * blockDim.x + threadIdx.x;
    unsigned e = t / W4;
    unsigned q = t % W4;
    if (e >= N_EDGES) return;
    int s = src[e];
    int d = dst[e];
    float4 v = ((const float4*)hin)[(size_t)s * W4 + q];
    red_add_v4(agg + (size_t)d * (W4 * 4) + q * 4, v);
}

// ---------------- dense conv: hout = relu(agg@Wrel + hin@Wroot + b) ---------
template <int KIN, bool L1>
__global__ void __launch_bounds__(128) conv_kernel(
    const float* __restrict__ Wrel,
    const float* __restrict__ Wroot,
    const float* __restrict__ b)
{
    const float* agg  = L1 ? g_agg0 : g_agg1;
    const float* hin  = L1 ? g_h0   : g_h1;
    float*       hout = L1 ? g_h1   : g_h2;

    __shared__ float sWrel[KIN * 64];
    __shared__ float sWroot[KIN * 64];
    __shared__ float sb[64];
    int tid = threadIdx.x;
    for (int i = tid; i < KIN * 64; i += blockDim.x) {
        sWrel[i]  = Wrel[i];
        sWroot[i] = Wroot[i];
    }
    if (tid < 64) sb[tid] = b[tid];
    __syncthreads();

    int n = blockIdx.x * blockDim.x + tid;
    if (n >= N_NODES) return;

    float acc[64];
#pragma unroll
    for (int j = 0; j < 64; j++) acc[j] = sb[j];

    const float4* arow = (const float4*)(agg + (size_t)n * KIN);
    const float4* hrow = (const float4*)(hin + (size_t)n * KIN);
#pragma unroll
    for (int k4 = 0; k4 < KIN / 4; k4++) {
        float4 av = arow[k4];
        float4 hv = hrow[k4];
        float aa[4] = {av.x, av.y, av.z, av.w};
        float hh[4] = {hv.x, hv.y, hv.z, hv.w};
#pragma unroll
        for (int kk = 0; kk < 4; kk++) {
            int k = k4 * 4 + kk;
            float a = aa[kk];
            float h = hh[kk];
#pragma unroll
            for (int j = 0; j < 64; j++)
                acc[j] += a * sWrel[k * 64 + j] + h * sWroot[k * 64 + j];
        }
    }

    float4* out = (float4*)(hout + (size_t)n * 64);
#pragma unroll
    for (int q = 0; q < 16; q++) {
        float4 v;
        v.x = fmaxf(acc[q * 4 + 0], 0.f);
        v.y = fmaxf(acc[q * 4 + 1], 0.f);
        v.z = fmaxf(acc[q * 4 + 2], 0.f);
        v.w = fmaxf(acc[q * 4 + 3], 0.f);
        out[q] = v;
    }
}

// ---------------- mean-pool over graphs -------------------------------------
__global__ void pool_kernel(const int* __restrict__ batch) {
    unsigned t = blockIdx.x * blockDim.x + threadIdx.x;
    unsigned n = t >> 4;       // 16 float4 chunks per 64-wide row
    unsigned q = t & 15;
    if (n >= N_NODES) return;
    int g = batch[n];
    float4 v = ((const float4*)g_h2)[(size_t)n * 16 + q];
    red_add_v4(g_pooled + (size_t)g * 64 + q * 4, v);
    if (q == 0) atomicAdd(&g_counts[g], 1);
}

// ---------------- classifier: out = (pooled/count) @ W_cls + b --------------
__global__ void __launch_bounds__(128) cls_kernel(
    const float* __restrict__ W_cls,
    const float* __restrict__ b_cls,
    float* __restrict__ out)
{
    __shared__ float sW[64 * 10];
    __shared__ float sb[10];
    int tid = threadIdx.x;
    for (int i = tid; i < 640; i += blockDim.x) sW[i] = W_cls[i];
    if (tid < 10) sb[tid] = b_cls[tid];
    __syncthreads();

    int g = blockIdx.x * blockDim.x + tid;
    if (g >= N_GRAPHS) return;
    float inv = 1.0f / fmaxf((float)g_counts[g], 1.0f);

    float acc[10];
#pragma unroll
    for (int j = 0; j < 10; j++) acc[j] = sb[j];
#pragma unroll 8
    for (int k = 0; k < 64; k++) {
        float p = g_pooled[(size_t)g * 64 + k] * inv;
#pragma unroll
        for (int j = 0; j < 10; j++) acc[j] += p * sW[k * 10 + j];
    }
#pragma unroll
    for (int j = 0; j < 10; j++) out[(size_t)g * 10 + j] = acc[j];
}

// ---------------- launch ------------------------------------------------------
extern "C" void kernel_launch(void* const* d_in, const int* in_sizes, int n_in,
                              void* d_out, int out_size)
{
    const int*   x         = (const int*)  d_in[0];
    const int*   edge_index= (const int*)  d_in[1];
    const int*   batch     = (const int*)  d_in[2];
    const float* shape_emb = (const float*)d_in[3];
    const float* color_emb = (const float*)d_in[4];
    const float* W_node    = (const float*)d_in[5];
    const float* b_node    = (const float*)d_in[6];
    const float* W1_rel    = (const float*)d_in[7];
    const float* W1_root   = (const float*)d_in[8];
    const float* b1        = (const float*)d_in[9];
    const float* W2_rel    = (const float*)d_in[10];
    const float* W2_root   = (const float*)d_in[11];
    const float* b2        = (const float*)d_in[12];
    const float* W_cls     = (const float*)d_in[13];
    const float* b_cls     = (const float*)d_in[14];
    float* out = (float*)d_out;

    const int* src = edge_index;            // edge_index[0, :]
    const int* dst = edge_index + N_EDGES;  // edge_index[1, :]

    zero_kernel<<<1024, 256>>>();

    node_embed_kernel<<<(N_NODES + 127) / 128, 128>>>(x, shape_emb, color_emb, W_node, b_node);

    // layer 1: width 32
    {
        unsigned threads = (unsigned)N_EDGES * 8;
        scatter_kernel<8, true><<<(threads + 255) / 256, 256>>>(src, dst);
        conv_kernel<32, true><<<(N_NODES + 127) / 128, 128>>>(W1_rel, W1_root, b1);
    }
    // layer 2: width 64
    {
        unsigned threads = (unsigned)N_EDGES * 16;
        scatter_kernel<16, false><<<(threads + 255) / 256, 256>>>(src, dst);
        conv_kernel<64, false><<<(N_NODES + 127) / 128, 128>>>(W2_rel, W2_root, b2);
    }

    pool_kernel<<<((unsigned)N_NODES * 16 + 255) / 256, 256>>>(batch);
    cls_kernel<<<(N_GRAPHS + 127) / 128, 128>>>(W_cls, b_cls, out);
}

// round 3
// speedup vs baseline: 1.4430x; 1.4430x over previous
#include <cuda_runtime.h>
#include <cuda_bf16.h>

#define N_NODES   100000
#define NODE_PAD  100096            // 782 * 128
#define N_EDGES   1000000
#define N_GRAPHS  1024
#define SCAN_BLK  512
#define N_SCAN_BLKS ((N_NODES + SCAN_BLK - 1) / SCAN_BLK)   // 196

// ---------------- scratch (device globals; zero-initialized at load) --------
__device__ __align__(16) float g_h0  [NODE_PAD * 32];
__device__ __align__(16) float g_agg0[NODE_PAD * 32];
__device__ __align__(16) float g_h1  [NODE_PAD * 64];
__device__ __align__(16) float g_agg1[NODE_PAD * 64];
__device__ __align__(16) float g_h2  [NODE_PAD * 64];
__device__ int g_deg[N_NODES];
__device__ int g_off[N_NODES + 1];
__device__ int g_cur[N_NODES];
__device__ int g_eidx[N_EDGES];
__device__ int g_bsum[N_SCAN_BLKS];
__device__ int g_gstart[N_GRAPHS + 1];

// ---------------- zero degree array each replay ------------------------------
__global__ void zero_deg_kernel() {
    int i = blockIdx.x * blockDim.x + threadIdx.x;
    if (i < N_NODES) g_deg[i] = 0;
}

// ---------------- CSR build ---------------------------------------------------
__global__ void count_kernel(const int* __restrict__ dst) {
    int e = blockIdx.x * blockDim.x + threadIdx.x;
    if (e < N_EDGES) atomicAdd(&g_deg[dst[e]], 1);
}

__global__ void __launch_bounds__(SCAN_BLK) scan1_kernel() {
    __shared__ int s[SCAN_BLK];
    int n = blockIdx.x * SCAN_BLK + threadIdx.x;
    s[threadIdx.x] = (n < N_NODES) ? g_deg[n] : 0;
    __syncthreads();
    for (int off = SCAN_BLK / 2; off > 0; off >>= 1) {
        if (threadIdx.x < off) s[threadIdx.x] += s[threadIdx.x + off];
        __syncthreads();
    }
    if (threadIdx.x == 0) g_bsum[blockIdx.x] = s[0];
}

__global__ void scan2_kernel() {
    if (threadIdx.x == 0) {
        int run = 0;
        for (int i = 0; i < N_SCAN_BLKS; i++) { int t = g_bsum[i]; g_bsum[i] = run; run += t; }
        g_off[N_NODES] = run;
    }
}

__global__ void __launch_bounds__(SCAN_BLK) scan3_kernel() {
    __shared__ int s[SCAN_BLK];
    int n = blockIdx.x * SCAN_BLK + threadIdx.x;
    int d = (n < N_NODES) ? g_deg[n] : 0;
    s[threadIdx.x] = d;
    __syncthreads();
    // Hillis-Steele inclusive scan
    for (int off = 1; off < SCAN_BLK; off <<= 1) {
        int v = (threadIdx.x >= off) ? s[threadIdx.x - off] : 0;
        __syncthreads();
        s[threadIdx.x] += v;
        __syncthreads();
    }
    if (n < N_NODES) {
        int o = g_bsum[blockIdx.x] + s[threadIdx.x] - d;   // exclusive
        g_off[n] = o;
        g_cur[n] = o;
    }
}

__global__ void fill_kernel(const int* __restrict__ src, const int* __restrict__ dst) {
    int e = blockIdx.x * blockDim.x + threadIdx.x;
    if (e >= N_EDGES) return;
    int d = dst[e];
    int pos = atomicAdd(&g_cur[d], 1);
    g_eidx[pos] = src[e];
}

// ---------------- graph boundaries (batch is sorted) -------------------------
__global__ void bounds_kernel(const int* __restrict__ batch) {
    int n = blockIdx.x * blockDim.x + threadIdx.x;
    if (n >= N_NODES) return;
    int b1 = batch[n];
    int b0 = (n == 0) ? -1 : batch[n - 1];
    for (int g = b0 + 1; g <= b1; g++) g_gstart[g] = n;
    if (n == N_NODES - 1)
        for (int g = b1 + 1; g <= N_GRAPHS; g++) g_gstart[g] = N_NODES;
}

// ---------------- node embedding: h0 = relu([s|c] @ W_node + b) -------------
__global__ void __launch_bounds__(128) node_embed_kernel(
    const int* __restrict__ x,
    const float* __restrict__ shape_emb,
    const float* __restrict__ color_emb,
    const float* __restrict__ W_node,
    const float* __restrict__ b_node)
{
    __shared__ float sW[16 * 32];
    __shared__ float sb[32];
    __shared__ float sS[64];
    __shared__ float sC[64];
    int tid = threadIdx.x;
    for (int i = tid; i < 16 * 32; i += blockDim.x) sW[i] = W_node[i];
    if (tid < 32) sb[tid] = b_node[tid];
    if (tid < 64) { sS[tid] = shape_emb[tid]; sC[tid] = color_emb[tid]; }
    __syncthreads();

    int n = blockIdx.x * blockDim.x + tid;
    if (n >= N_NODES) return;
    int sh = x[2 * n];
    int co = x[2 * n + 1];

    float acc[32];
#pragma unroll
    for (int j = 0; j < 32; j++) acc[j] = sb[j];
#pragma unroll
    for (int k = 0; k < 8; k++) {
        float s = sS[sh * 8 + k];
        float c = sC[co * 8 + k];
#pragma unroll
        for (int j = 0; j < 32; j++)
            acc[j] += s * sW[k * 32 + j] + c * sW[(8 + k) * 32 + j];
    }
    float4* out = (float4*)&g_h0[(size_t)n * 32];
#pragma unroll
    for (int q = 0; q < 8; q++) {
        float4 v;
        v.x = fmaxf(acc[q * 4 + 0], 0.f);
        v.y = fmaxf(acc[q * 4 + 1], 0.f);
        v.z = fmaxf(acc[q * 4 + 2], 0.f);
        v.w = fmaxf(acc[q * 4 + 3], 0.f);
        out[q] = v;
    }
}

// ---------------- gather aggregation (CSR, warp per node) -------------------
__global__ void __launch_bounds__(256) gather32_kernel() {
    int w = (blockIdx.x * 256 + threadIdx.x) >> 5;
    int lane = threadIdx.x & 31;
    if (w >= N_NODES) return;
    int s0 = g_off[w], s1 = g_off[w + 1];
    float acc = 0.f;
    int i = s0;
    for (; i + 1 < s1; i += 2) {
        int sa = __ldg(&g_eidx[i]);
        int sb = __ldg(&g_eidx[i + 1]);
        acc += g_h0[(size_t)sa * 32 + lane];
        acc += g_h0[(size_t)sb * 32 + lane];
    }
    if (i < s1) {
        int sa = __ldg(&g_eidx[i]);
        acc += g_h0[(size_t)sa * 32 + lane];
    }
    g_agg0[(size_t)w * 32 + lane] = acc;
}

__global__ void __launch_bounds__(256) gather64_kernel() {
    int w = (blockIdx.x * 256 + threadIdx.x) >> 5;
    int lane = threadIdx.x & 31;
    if (w >= N_NODES) return;
    int s0 = g_off[w], s1 = g_off[w + 1];
    float2 acc = make_float2(0.f, 0.f);
    int i = s0;
    for (; i + 1 < s1; i += 2) {
        int sa = __ldg(&g_eidx[i]);
        int sb = __ldg(&g_eidx[i + 1]);
        float2 va = ((const float2*)g_h1)[(size_t)sa * 32 + lane];
        float2 vb = ((const float2*)g_h1)[(size_t)sb * 32 + lane];
        acc.x += va.x + vb.x;
        acc.y += va.y + vb.y;
    }
    if (i < s1) {
        int sa = __ldg(&g_eidx[i]);
        float2 va = ((const float2*)g_h1)[(size_t)sa * 32 + lane];
        acc.x += va.x;
        acc.y += va.y;
    }
    ((float2*)g_agg1)[(size_t)w * 32 + lane] = acc;
}

// ---------------- dense conv: hout = relu(agg@Wrel + hin@Wroot + b) ---------
// Register-blocked: 128 threads, 128 nodes per block.
// thread: cg = tid>>5 owns 16 cols, ng = tid&31; nodes ng + 32*{0..3}.
// L1 selects (g_agg0,g_h0)->g_h1 (KIN=32) vs (g_agg1,g_h1)->g_h2 (KIN=64).
template <int KIN, bool L1>
__global__ void __launch_bounds__(128) conv_kernel(
    const float* __restrict__ Wrel,
    const float* __restrict__ Wroot,
    const float* __restrict__ b)
{
    const float* agg  = L1 ? g_agg0 : g_agg1;
    const float* hin  = L1 ? g_h0   : g_h1;
    float*       hout = L1 ? g_h1   : g_h2;

    constexpr int KC = 8;           // k-chunk
    constexpr int RS = 129;         // padded row stride (words) for staged inputs
    __shared__ float sWrel[KIN * 64];
    __shared__ float sWroot[KIN * 64];
    __shared__ float sA[KC * RS];
    __shared__ float sH[KC * RS];

    int tid = threadIdx.x;
    for (int i = tid; i < KIN * 64; i += 128) {
        sWrel[i]  = Wrel[i];
        sWroot[i] = Wroot[i];
    }

    int cg = tid >> 5;
    int ng = tid & 31;
    int base = blockIdx.x * 128;

    float acc[4][16];
    {
        float bj[16];
#pragma unroll
        for (int j = 0; j < 16; j++) bj[j] = b[cg * 16 + j];
#pragma unroll
        for (int i = 0; i < 4; i++)
#pragma unroll
            for (int j = 0; j < 16; j++) acc[i][j] = bj[j];
    }
    __syncthreads();

    int r = tid >> 1;         // 0..63
    int v = tid & 1;          // 0..1 : which float4 of the 8-float chunk
    for (int kc = 0; kc < KIN; kc += KC) {
        // stage KC x 128 (transposed to k-major) for both inputs
#pragma unroll
        for (int p = 0; p < 2; p++) {
            int row = p * 64 + r;
            const float4 a4 = *(const float4*)(agg + (size_t)(base + row) * KIN + kc + v * 4);
            const float4 h4 = *(const float4*)(hin + (size_t)(base + row) * KIN + kc + v * 4);
            sA[(v * 4 + 0) * RS + row] = a4.x;
            sA[(v * 4 + 1) * RS + row] = a4.y;
            sA[(v * 4 + 2) * RS + row] = a4.z;
            sA[(v * 4 + 3) * RS + row] = a4.w;
            sH[(v * 4 + 0) * RS + row] = h4.x;
            sH[(v * 4 + 1) * RS + row] = h4.y;
            sH[(v * 4 + 2) * RS + row] = h4.z;
            sH[(v * 4 + 3) * RS + row] = h4.w;
        }
        __syncthreads();

#pragma unroll
        for (int kk = 0; kk < KC; kk++) {
            int k = kc + kk;
            float wr[16], wo[16];
#pragma unroll
            for (int j = 0; j < 16; j++) {
                wr[j] = sWrel[k * 64 + cg * 16 + j];
                wo[j] = sWroot[k * 64 + cg * 16 + j];
            }
#pragma unroll
            for (int i = 0; i < 4; i++) {
                float a = sA[kk * RS + ng + 32 * i];
                float h = sH[kk * RS + ng + 32 * i];
#pragma unroll
                for (int j = 0; j < 16; j++)
                    acc[i][j] = fmaf(a, wr[j], fmaf(h, wo[j], acc[i][j]));
            }
        }
        __syncthreads();
    }

    // write out: rows base+ng+32i, cols cg*16..cg*16+15 (4 float4 stores)
#pragma unroll
    for (int i = 0; i < 4; i++) {
        float* orow = hout + (size_t)(base + ng + 32 * i) * 64 + cg * 16;
#pragma unroll
        for (int q = 0; q < 4; q++) {
            float4 o;
            o.x = fmaxf(acc[i][q * 4 + 0], 0.f);
            o.y = fmaxf(acc[i][q * 4 + 1], 0.f);
            o.z = fmaxf(acc[i][q * 4 + 2], 0.f);
            o.w = fmaxf(acc[i][q * 4 + 3], 0.f);
            ((float4*)orow)[q] = o;
        }
    }
}

// ---------------- fused mean-pool + classifier ------------------------------
__global__ void __launch_bounds__(64) poolcls_kernel(
    const float* __restrict__ W_cls,
    const float* __restrict__ b_cls,
    float* __restrict__ out)
{
    int g = blockIdx.x;
    int tid = threadIdx.x;
    int s = g_gstart[g], e = g_gstart[g + 1];
    float acc = 0.f;
    for (int n = s; n < e; n++) acc += g_h2[(size_t)n * 64 + tid];
    float cnt = fmaxf((float)(e - s), 1.0f);
    __shared__ float sp[64];
    sp[tid] = acc / cnt;
    __syncthreads();
    if (tid < 10) {
        float dot = b_cls[tid];
#pragma unroll 8
        for (int k = 0; k < 64; k++) dot += sp[k] * W_cls[k * 10 + tid];
        out[(size_t)g * 10 + tid] = dot;
    }
}

// ---------------- launch ------------------------------------------------------
extern "C" void kernel_launch(void* const* d_in, const int* in_sizes, int n_in,
                              void* d_out, int out_size)
{
    const int*   x         = (const int*)  d_in[0];
    const int*   edge_index= (const int*)  d_in[1];
    const int*   batch     = (const int*)  d_in[2];
    const float* shape_emb = (const float*)d_in[3];
    const float* color_emb = (const float*)d_in[4];
    const float* W_node    = (const float*)d_in[5];
    const float* b_node    = (const float*)d_in[6];
    const float* W1_rel    = (const float*)d_in[7];
    const float* W1_root   = (const float*)d_in[8];
    const float* b1        = (const float*)d_in[9];
    const float* W2_rel    = (const float*)d_in[10];
    const float* W2_root   = (const float*)d_in[11];
    const float* b2        = (const float*)d_in[12];
    const float* W_cls     = (const float*)d_in[13];
    const float* b_cls     = (const float*)d_in[14];
    float* out = (float*)d_out;

    const int* src = edge_index;            // edge_index[0, :]
    const int* dst = edge_index + N_EDGES;  // edge_index[1, :]

    // CSR build + boundaries + embedding
    zero_deg_kernel<<<(N_NODES + 255) / 256, 256>>>();
    count_kernel<<<(N_EDGES + 255) / 256, 256>>>(dst);
    scan1_kernel<<<N_SCAN_BLKS, SCAN_BLK>>>();
    scan2_kernel<<<1, 32>>>();
    scan3_kernel<<<N_SCAN_BLKS, SCAN_BLK>>>();
    fill_kernel<<<(N_EDGES + 255) / 256, 256>>>(src, dst);
    bounds_kernel<<<(N_NODES + 255) / 256, 256>>>(batch);
    node_embed_kernel<<<(N_NODES + 127) / 128, 128>>>(x, shape_emb, color_emb, W_node, b_node);

    // layer 1
    gather32_kernel<<<(N_NODES * 32 + 255) / 256, 256>>>();
    conv_kernel<32, true><<<NODE_PAD / 128, 128>>>(W1_rel, W1_root, b1);

    // layer 2
    gather64_kernel<<<(N_NODES * 32 + 255) / 256, 256>>>();
    conv_kernel<64, false><<<NODE_PAD / 128, 128>>>(W2_rel, W2_root, b2);

    // pool + classify
    poolcls_kernel<<<N_GRAPHS, 64>>>(W_cls, b_cls, out);
}

// round 4
// speedup vs baseline: 1.6854x; 1.1680x over previous
#include <cuda_runtime.h>
#include <cuda_bf16.h>
#include <cstdint>

#define N_NODES   100000
#define NODE_PAD  100096            // 782 * 128
#define N_EDGES   1000000
#define N_GRAPHS  1024
#define SCAN_BLK  512
#define N_SCAN_BLKS ((N_NODES + SCAN_BLK - 1) / SCAN_BLK)   // 196
#define EB ((N_EDGES + 255) / 256)  // 3907 edge blocks in prologue
#define NB ((N_NODES + 255) / 256)  // 391 node blocks in prologue

// ---------------- scratch (device globals; zero-initialized at load) --------
// Invariant: g_deg is zero on entry to every kernel_launch call. It starts
// zero (BSS) and fill_kernel re-zeroes it at the end of every call, after
// its last use (scan3). Pad rows of g_agg* / g_h0 are never written and stay
// zero; pad rows of g_h1/g_h2 are rewritten identically every call.
__device__ __align__(16) float g_h0  [NODE_PAD * 32];
__device__ __align__(16) float g_agg0[NODE_PAD * 32];
__device__ __align__(16) float g_h1  [NODE_PAD * 64];
__device__ __align__(16) float g_agg1[NODE_PAD * 64];
__device__ __align__(16) float g_h2  [NODE_PAD * 64];
__device__ int g_deg[N_NODES];
__device__ int g_off[N_NODES + 1];
__device__ int g_cur[N_NODES];
__device__ int g_eidx[N_EDGES];
__device__ int g_bsum[N_SCAN_BLKS];
__device__ int g_gstart[N_GRAPHS + 1];

// ---------------- fused prologue: edge count | bounds + node embed ----------
__global__ void __launch_bounds__(256) prologue_kernel(
    const int* __restrict__ dst,
    const int* __restrict__ batch,
    const int* __restrict__ x,
    const float* __restrict__ shape_emb,
    const float* __restrict__ color_emb,
    const float* __restrict__ W_node,
    const float* __restrict__ b_node)
{
    int tid = threadIdx.x;
    if (blockIdx.x < EB) {
        // role 1: degree count
        int e = blockIdx.x * 256 + tid;
        if (e < N_EDGES) atomicAdd(&g_deg[dst[e]], 1);
        return;
    }
    // role 2: graph bounds + node embedding
    int n = (blockIdx.x - EB) * 256 + tid;

    __shared__ float sW[16 * 32];
    __shared__ float sb[32];
    __shared__ float sS[64];
    __shared__ float sC[64];
    for (int i = tid; i < 16 * 32; i += 256) sW[i] = W_node[i];
    if (tid < 32) sb[tid] = b_node[tid];
    if (tid < 64) { sS[tid] = shape_emb[tid]; sC[tid] = color_emb[tid]; }
    __syncthreads();

    if (n >= N_NODES) return;

    // bounds (batch is sorted)
    {
        int b1 = batch[n];
        int b0 = (n == 0) ? -1 : batch[n - 1];
        for (int g = b0 + 1; g <= b1; g++) g_gstart[g] = n;
        if (n == N_NODES - 1)
            for (int g = b1 + 1; g <= N_GRAPHS; g++) g_gstart[g] = N_NODES;
    }

    // embedding
    int sh = x[2 * n];
    int co = x[2 * n + 1];
    float acc[32];
#pragma unroll
    for (int j = 0; j < 32; j++) acc[j] = sb[j];
#pragma unroll
    for (int k = 0; k < 8; k++) {
        float s = sS[sh * 8 + k];
        float c = sC[co * 8 + k];
#pragma unroll
        for (int j = 0; j < 32; j++)
            acc[j] += s * sW[k * 32 + j] + c * sW[(8 + k) * 32 + j];
    }
    float4* out = (float4*)&g_h0[(size_t)n * 32];
#pragma unroll
    for (int q = 0; q < 8; q++) {
        float4 v;
        v.x = fmaxf(acc[q * 4 + 0], 0.f);
        v.y = fmaxf(acc[q * 4 + 1], 0.f);
        v.z = fmaxf(acc[q * 4 + 2], 0.f);
        v.w = fmaxf(acc[q * 4 + 3], 0.f);
        out[q] = v;
    }
}

// ---------------- CSR scan cascade ------------------------------------------
__global__ void __launch_bounds__(SCAN_BLK) scan1_kernel() {
    __shared__ int s[SCAN_BLK];
    int n = blockIdx.x * SCAN_BLK + threadIdx.x;
    s[threadIdx.x] = (n < N_NODES) ? g_deg[n] : 0;
    __syncthreads();
    for (int off = SCAN_BLK / 2; off > 0; off >>= 1) {
        if (threadIdx.x < off) s[threadIdx.x] += s[threadIdx.x + off];
        __syncthreads();
    }
    if (threadIdx.x == 0) g_bsum[blockIdx.x] = s[0];
}

// parallel exclusive scan of 196 block sums (single block)
__global__ void __launch_bounds__(256) scan2_kernel() {
    __shared__ int s[256];
    int tid = threadIdx.x;
    int v = (tid < N_SCAN_BLKS) ? g_bsum[tid] : 0;
    s[tid] = v;
    __syncthreads();
    for (int off = 1; off < 256; off <<= 1) {
        int t = (tid >= off) ? s[tid - off] : 0;
        __syncthreads();
        s[tid] += t;
        __syncthreads();
    }
    if (tid < N_SCAN_BLKS) g_bsum[tid] = s[tid] - v;   // exclusive
    if (tid == 255) g_off[N_NODES] = s[255];
}

__global__ void __launch_bounds__(SCAN_BLK) scan3_kernel() {
    __shared__ int s[SCAN_BLK];
    int n = blockIdx.x * SCAN_BLK + threadIdx.x;
    int d = (n < N_NODES) ? g_deg[n] : 0;
    s[threadIdx.x] = d;
    __syncthreads();
    for (int off = 1; off < SCAN_BLK; off <<= 1) {
        int v = (threadIdx.x >= off) ? s[threadIdx.x - off] : 0;
        __syncthreads();
        s[threadIdx.x] += v;
        __syncthreads();
    }
    if (n < N_NODES) {
        int o = g_bsum[blockIdx.x] + s[threadIdx.x] - d;   // exclusive
        g_off[n] = o;
        g_cur[n] = o;
    }
}

// fill CSR; also restore the g_deg==0 invariant for the next call
__global__ void fill_kernel(const int* __restrict__ src, const int* __restrict__ dst) {
    int e = blockIdx.x * blockDim.x + threadIdx.x;
    if (e < N_NODES) g_deg[e] = 0;
    if (e >= N_EDGES) return;
    int d = dst[e];
    int pos = atomicAdd(&g_cur[d], 1);
    g_eidx[pos] = src[e];
}

// ---------------- gather aggregation (CSR, warp per node) -------------------
__global__ void __launch_bounds__(256) gather32_kernel() {
    int w = (blockIdx.x * 256 + threadIdx.x) >> 5;
    int lane = threadIdx.x & 31;
    if (w >= N_NODES) return;
    int s0 = g_off[w], s1 = g_off[w + 1];
    float acc = 0.f;
    int i = s0;
    for (; i + 3 < s1; i += 4) {
        int sa = __ldg(&g_eidx[i]);
        int sb = __ldg(&g_eidx[i + 1]);
        int sc = __ldg(&g_eidx[i + 2]);
        int sd = __ldg(&g_eidx[i + 3]);
        float va = g_h0[(size_t)sa * 32 + lane];
        float vb = g_h0[(size_t)sb * 32 + lane];
        float vc = g_h0[(size_t)sc * 32 + lane];
        float vd = g_h0[(size_t)sd * 32 + lane];
        acc += (va + vb) + (vc + vd);
    }
    for (; i < s1; i++) {
        int sa = __ldg(&g_eidx[i]);
        acc += g_h0[(size_t)sa * 32 + lane];
    }
    g_agg0[(size_t)w * 32 + lane] = acc;
}

__global__ void __launch_bounds__(256) gather64_kernel() {
    int w = (blockIdx.x * 256 + threadIdx.x) >> 5;
    int lane = threadIdx.x & 31;
    if (w >= N_NODES) return;
    int s0 = g_off[w], s1 = g_off[w + 1];
    float2 acc = make_float2(0.f, 0.f);
    int i = s0;
    for (; i + 3 < s1; i += 4) {
        int sa = __ldg(&g_eidx[i]);
        int sb = __ldg(&g_eidx[i + 1]);
        int sc = __ldg(&g_eidx[i + 2]);
        int sd = __ldg(&g_eidx[i + 3]);
        float2 va = ((const float2*)g_h1)[(size_t)sa * 32 + lane];
        float2 vb = ((const float2*)g_h1)[(size_t)sb * 32 + lane];
        float2 vc = ((const float2*)g_h1)[(size_t)sc * 32 + lane];
        float2 vd = ((const float2*)g_h1)[(size_t)sd * 32 + lane];
        acc.x += (va.x + vb.x) + (vc.x + vd.x);
        acc.y += (va.y + vb.y) + (vc.y + vd.y);
    }
    for (; i < s1; i++) {
        int sa = __ldg(&g_eidx[i]);
        float2 va = ((const float2*)g_h1)[(size_t)sa * 32 + lane];
        acc.x += va.x;
        acc.y += va.y;
    }
    ((float2*)g_agg1)[(size_t)w * 32 + lane] = acc;
}

// ---------------- tf32 tensor-core conv -------------------------------------
// hout[M,64] = relu([agg|hin] @ [Wrel;Wroot] + b), K = 2*KIN, via
// mma.sync.aligned.m16n8k8.row.col.f32.tf32.tf32.f32
// Block: 256 threads, 128 nodes. Warp grid 4m x 2n: warp wm=wid>>1 owns rows
// [wm*32,+32) (2 m16 tiles), wn=wid&1 owns cols [wn*32,+32) (4 n8 tiles).
__device__ __forceinline__ uint32_t f2tf32(float f) {
    uint32_t u;
    asm("cvt.rna.tf32.f32 %0, %1;" : "=r"(u) : "f"(f));
    return u;
}

__device__ __forceinline__ void mma_tf32(float c[4],
                                         uint32_t a0, uint32_t a1, uint32_t a2, uint32_t a3,
                                         uint32_t b0, uint32_t b1) {
    asm volatile(
        "mma.sync.aligned.m16n8k8.row.col.f32.tf32.tf32.f32 "
        "{%0,%1,%2,%3}, {%4,%5,%6,%7}, {%8,%9}, {%0,%1,%2,%3};"
        : "+f"(c[0]), "+f"(c[1]), "+f"(c[2]), "+f"(c[3])
        : "r"(a0), "r"(a1), "r"(a2), "r"(a3), "r"(b0), "r"(b1));
}

template <int KIN, bool L1>
__global__ void __launch_bounds__(256) conv_tf32_kernel(
    const float* __restrict__ Wrel,
    const float* __restrict__ Wroot,
    const float* __restrict__ b)
{
    const float* agg  = L1 ? g_agg0 : g_agg1;
    const float* hin  = L1 ? g_h0   : g_h1;
    float*       hout = L1 ? g_h1   : g_h2;

    constexpr int K2 = 2 * KIN;
    constexpr int STEPS = K2 / 8;
    constexpr int LDB = 72;                 // padded stride: conflict-free b-frag LDS

    __shared__ uint32_t sW[K2 * LDB];       // combined [Wrel;Wroot] in tf32 bits
    __shared__ float sb[64];

    int tid = threadIdx.x;
    for (int i = tid; i < K2 * 64; i += 256) {
        int k = i >> 6, n = i & 63;
        float v = (k < KIN) ? Wrel[k * 64 + n] : Wroot[(k - KIN) * 64 + n];
        sW[k * LDB + n] = f2tf32(v);
    }
    if (tid < 64) sb[tid] = b[tid];
    __syncthreads();

    int lane = tid & 31, wid = tid >> 5;
    int wm = wid >> 1, wn = wid & 1;
    int r4 = lane >> 2, c4 = lane & 3;
    int base = blockIdx.x * 128;
    int node0 = base + wm * 32 + r4;        // + t*16 (+8) selects the row

    float acc[2][4][4];
#pragma unroll
    for (int t = 0; t < 2; t++)
#pragma unroll
        for (int u = 0; u < 4; u++) {
            int col = wn * 32 + u * 8 + c4 * 2;
            acc[t][u][0] = sb[col];
            acc[t][u][1] = sb[col + 1];
            acc[t][u][2] = sb[col];
            acc[t][u][3] = sb[col + 1];
        }

#pragma unroll
    for (int s = 0; s < STEPS; s++) {
        const float* A = (s * 8 < KIN) ? agg : hin;
        int koff = s * 8 - ((s * 8 < KIN) ? 0 : KIN) + c4;

        uint32_t a[2][4];
#pragma unroll
        for (int t = 0; t < 2; t++) {
            const float* row0 = A + (size_t)(node0 + t * 16) * KIN + koff;
            const float* row8 = A + (size_t)(node0 + t * 16 + 8) * KIN + koff;
            a[t][0] = f2tf32(__ldg(row0));
            a[t][1] = f2tf32(__ldg(row8));
            a[t][2] = f2tf32(__ldg(row0 + 4));
            a[t][3] = f2tf32(__ldg(row8 + 4));
        }

        int krow = s * 8 + c4;
        uint32_t bf[4][2];
#pragma unroll
        for (int u = 0; u < 4; u++) {
            int col = wn * 32 + u * 8 + r4;
            bf[u][0] = sW[krow * LDB + col];
            bf[u][1] = sW[(krow + 4) * LDB + col];
        }

#pragma unroll
        for (int t = 0; t < 2; t++)
#pragma unroll
            for (int u = 0; u < 4; u++)
                mma_tf32(acc[t][u], a[t][0], a[t][1], a[t][2], a[t][3],
                         bf[u][0], bf[u][1]);
    }

    // store with relu; C frag: c0,c1 -> (row, col..col+1), c2,c3 -> (row+8, ..)
#pragma unroll
    for (int t = 0; t < 2; t++) {
        int row = base + wm * 32 + t * 16 + r4;
#pragma unroll
        for (int u = 0; u < 4; u++) {
            int col = wn * 32 + u * 8 + c4 * 2;
            float2 lo = make_float2(fmaxf(acc[t][u][0], 0.f), fmaxf(acc[t][u][1], 0.f));
            float2 hi = make_float2(fmaxf(acc[t][u][2], 0.f), fmaxf(acc[t][u][3], 0.f));
            *(float2*)&hout[(size_t)row * 64 + col]       = lo;
            *(float2*)&hout[(size_t)(row + 8) * 64 + col] = hi;
        }
    }
}

// ---------------- fused mean-pool + classifier ------------------------------
__global__ void __launch_bounds__(64) poolcls_kernel(
    const float* __restrict__ W_cls,
    const float* __restrict__ b_cls,
    float* __restrict__ out)
{
    int g = blockIdx.x;
    int tid = threadIdx.x;
    int s = g_gstart[g], e = g_gstart[g + 1];
    float acc = 0.f;
    for (int n = s; n < e; n++) acc += g_h2[(size_t)n * 64 + tid];
    float cnt = fmaxf((float)(e - s), 1.0f);
    __shared__ float sp[64];
    sp[tid] = acc / cnt;
    __syncthreads();
    if (tid < 10) {
        float dot = b_cls[tid];
#pragma unroll 8
        for (int k = 0; k < 64; k++) dot += sp[k] * W_cls[k * 10 + tid];
        out[(size_t)g * 10 + tid] = dot;
    }
}

// ---------------- launch ------------------------------------------------------
extern "C" void kernel_launch(void* const* d_in, const int* in_sizes, int n_in,
                              void* d_out, int out_size)
{
    const int*   x         = (const int*)  d_in[0];
    const int*   edge_index= (const int*)  d_in[1];
    const int*   batch     = (const int*)  d_in[2];
    const float* shape_emb = (const float*)d_in[3];
    const float* color_emb = (const float*)d_in[4];
    const float* W_node    = (const float*)d_in[5];
    const float* b_node    = (const float*)d_in[6];
    const float* W1_rel    = (const float*)d_in[7];
    const float* W1_root   = (const float*)d_in[8];
    const float* b1        = (const float*)d_in[9];
    const float* W2_rel    = (const float*)d_in[10];
    const float* W2_root   = (const float*)d_in[11];
    const float* b2        = (const float*)d_in[12];
    const float* W_cls     = (const float*)d_in[13];
    const float* b_cls     = (const float*)d_in[14];
    float* out = (float*)d_out;

    const int* src = edge_index;            // edge_index[0, :]
    const int* dst = edge_index + N_EDGES;  // edge_index[1, :]

    prologue_kernel<<<EB + NB, 256>>>(dst, batch, x, shape_emb, color_emb, W_node, b_node);
    scan1_kernel<<<N_SCAN_BLKS, SCAN_BLK>>>();
    scan2_kernel<<<1, 256>>>();
    scan3_kernel<<<N_SCAN_BLKS, SCAN_BLK>>>();
    fill_kernel<<<(N_EDGES + 255) / 256, 256>>>(src, dst);

    gather32_kernel<<<(N_NODES * 32 + 255) / 256, 256>>>();
    conv_tf32_kernel<32, true><<<NODE_PAD / 128, 256>>>(W1_rel, W1_root, b1);

    gather64_kernel<<<(N_NODES * 32 + 255) / 256, 256>>>();
    conv_tf32_kernel<64, false><<<NODE_PAD / 128, 256>>>(W2_rel, W2_root, b2);

    poolcls_kernel<<<N_GRAPHS, 64>>>(W_cls, b_cls, out);
}